// round 1
// baseline (speedup 1.0000x reference)
#include <cuda_runtime.h>
#include <math.h>

// Problem constants
#define Bn     2
#define Tn     4096
#define Dn     2048
#define Hn     16
#define DH     128
#define MROWS  8192   // B*T
#define NCOLS  6144   // 3*D
#define KDIM   2048

// Tiling
#define BM 128
#define BN 128
#define BK 16
#define TM 8
#define TN 8

__global__ __launch_bounds__(256, 2)
void qkv_rms_rope_kernel(const float* __restrict__ x,
                         const float* __restrict__ W,
                         const float* __restrict__ gq,
                         const float* __restrict__ gk,
                         const float* __restrict__ pos,
                         float* __restrict__ out)
{
    __shared__ float As[BK][BM + 4];   // +4 pad: keeps 16B row alignment, spreads store banks
    __shared__ float Bs[BK][BN];

    const int tid = threadIdx.x;       // 0..255
    const int tx  = tid & 15;          // output col group (8 cols each)
    const int ty  = tid >> 4;          // output row group (8 rows each)
    const int row0 = blockIdx.y * BM;
    const int col0 = blockIdx.x * BN;

    // A-tile load mapping: 128 rows x 16 k. Each thread: 2 x float4.
    const int ar  = tid >> 2;          // rows 0..63 (+64 on second pass)
    const int ak4 = (tid & 3) * 4;     // k offset {0,4,8,12}
    // B-tile load mapping: 16 k x 128 cols. Each thread: 2 x float4.
    const int bk  = tid >> 5;          // k rows 0..7 (+8 on second pass)
    const int bc4 = (tid & 31) * 4;    // col offset

    float acc[TM][TN];
    #pragma unroll
    for (int i = 0; i < TM; i++)
        #pragma unroll
        for (int j = 0; j < TN; j++)
            acc[i][j] = 0.0f;

    for (int k0 = 0; k0 < KDIM; k0 += BK) {
        // ---- load A tile (transposed into As[k][m]) ----
        #pragma unroll
        for (int h = 0; h < 2; h++) {
            const int r = ar + h * 64;
            const float4 a = *(const float4*)(x + (size_t)(row0 + r) * KDIM + k0 + ak4);
            As[ak4 + 0][r] = a.x;
            As[ak4 + 1][r] = a.y;
            As[ak4 + 2][r] = a.z;
            As[ak4 + 3][r] = a.w;
        }
        // ---- load B tile ----
        #pragma unroll
        for (int h = 0; h < 2; h++) {
            const int kk = bk + h * 8;
            *(float4*)(&Bs[kk][bc4]) =
                *(const float4*)(W + (size_t)(k0 + kk) * NCOLS + col0 + bc4);
        }
        __syncthreads();

        // ---- FFMA mainloop ----
        #pragma unroll
        for (int kk = 0; kk < BK; kk++) {
            float af[TM], bf[TN];
            const float4 a0 = *(const float4*)(&As[kk][ty * TM + 0]);
            const float4 a1 = *(const float4*)(&As[kk][ty * TM + 4]);
            af[0]=a0.x; af[1]=a0.y; af[2]=a0.z; af[3]=a0.w;
            af[4]=a1.x; af[5]=a1.y; af[6]=a1.z; af[7]=a1.w;
            const float4 b0 = *(const float4*)(&Bs[kk][tx * TN + 0]);
            const float4 b1 = *(const float4*)(&Bs[kk][tx * TN + 4]);
            bf[0]=b0.x; bf[1]=b0.y; bf[2]=b0.z; bf[3]=b0.w;
            bf[4]=b1.x; bf[5]=b1.y; bf[6]=b1.z; bf[7]=b1.w;
            #pragma unroll
            for (int i = 0; i < TM; i++)
                #pragma unroll
                for (int j = 0; j < TN; j++)
                    acc[i][j] = fmaf(af[i], bf[j], acc[i][j]);
        }
        __syncthreads();
    }

    // ================= Epilogue =================
    // col0 is a multiple of 128 = Dh, so this block covers exactly one head's
    // columns for one of {q,k,v}. region: 0=q, 1=k, 2=v.
    const int region = col0 >> 11;          // /2048
    const int colr0  = col0 & 2047;         // column within region
    float* const outbase = out + (size_t)region * ((size_t)MROWS * Dn);

    if (region == 2) {
        // V: passthrough
        #pragma unroll
        for (int i = 0; i < TM; i++) {
            const int r = row0 + ty * TM + i;
            float* p = outbase + (size_t)r * Dn + colr0 + tx * TN;
            *(float4*)(p + 0) = make_float4(acc[i][0], acc[i][1], acc[i][2], acc[i][3]);
            *(float4*)(p + 4) = make_float4(acc[i][4], acc[i][5], acc[i][6], acc[i][7]);
        }
        return;
    }

    const float* const g = (region == 0) ? gq : gk;
    float gv[TN];
    #pragma unroll
    for (int j = 0; j < TN; j++) gv[j] = g[tx * TN + j];   // head-local column

    // --- RMSNorm: per-row sum of squares across the 128 head columns ---
    // lane = (ty&1)*16 + tx ; xor masks 1,2,4,8 mix only tx bits -> reduce over tx.
    float rinv[TM];
    #pragma unroll
    for (int i = 0; i < TM; i++) {
        float ss = 0.0f;
        #pragma unroll
        for (int j = 0; j < TN; j++) ss += acc[i][j] * acc[i][j];
        ss += __shfl_xor_sync(0xffffffffu, ss, 1);
        ss += __shfl_xor_sync(0xffffffffu, ss, 2);
        ss += __shfl_xor_sync(0xffffffffu, ss, 4);
        ss += __shfl_xor_sync(0xffffffffu, ss, 8);
        rinv[i] = rsqrtf(ss * (1.0f / (float)DH) + 1e-6f);
    }

    // --- RoPE: pair (c, c+64); xor-8 on lane swaps tx <-> tx^8 (same ty) ---
    const float NLOG = -13.287712379549449f / 64.0f;   // -log2(10000)/64
    #pragma unroll
    for (int i = 0; i < TM; i++) {
        const int r = row0 + ty * TM + i;
        const float p = pos[r & (Tn - 1)];
        float o[TN];
        #pragma unroll
        for (int j = 0; j < TN; j++) {
            const float val = acc[i][j] * rinv[i] * gv[j];
            const int   c   = tx * TN + j;
            const float invf = exp2f((float)(c & 63) * NLOG);
            float s, cs;
            sincosf(p * invf, &s, &cs);
            const float other = __shfl_xor_sync(0xffffffffu, val, 8);
            // tx<8: c in [0,64): x1=val, x2=other -> x1*cos - x2*sin
            // tx>=8: c in [64,128): x1=other, x2=val -> x1*sin + x2*cos
            o[j] = (tx < 8) ? (val * cs - other * s) : (other * s + val * cs);
        }
        float* q = outbase + (size_t)r * Dn + colr0 + tx * TN;
        *(float4*)(q + 0) = make_float4(o[0], o[1], o[2], o[3]);
        *(float4*)(q + 4) = make_float4(o[4], o[5], o[6], o[7]);
    }
}

extern "C" void kernel_launch(void* const* d_in, const int* in_sizes, int n_in,
                              void* d_out, int out_size) {
    const float* x   = (const float*)d_in[0];
    const float* W   = (const float*)d_in[1];
    const float* gq  = (const float*)d_in[2];
    const float* gk  = (const float*)d_in[3];
    const float* pos = (const float*)d_in[4];
    float* out = (float*)d_out;

    dim3 grid(NCOLS / BN, MROWS / BM);   // (48, 64)
    qkv_rms_rope_kernel<<<grid, 256>>>(x, W, gq, gk, pos, out);
}

// round 4
// speedup vs baseline: 1.5655x; 1.5655x over previous
#include <cuda_runtime.h>
#include <cuda_bf16.h>
#include <cstdint>
#include <math.h>

#define MROWS  8192
#define KD     2048
#define NCOLS  6144
#define K3     6144          // 3*KD (hi, lo, hi segments)
#define DOUT   2048
#define Tn     4096
#define NSTAGE 192           // K3 / 32
#define ROWB   80            // padded smem row stride (32 bf16 = 64B data + 16B pad)
#define ASTG   (128*ROWB)    // 10240
#define STAGE_BYTES (2*ASTG) // A tile + B tile
#define NPIPE  4
#define SMEM_TOTAL (NPIPE*STAGE_BYTES)   // 81920 >= epilogue tile 128*132*4 = 67584

// ---------------- static scratch ----------------
__device__ __align__(1024) __nv_bfloat16 g_A[(size_t)MROWS * K3];   // ~100 MB
__device__ __align__(1024) __nv_bfloat16 g_B[(size_t)NCOLS * K3];   // ~75 MB
__device__ float g_posv[Tn];

// ---------------- PTX helpers ----------------
__device__ __forceinline__ uint32_t smem_u32(const void* p) {
    uint32_t a;
    asm("{ .reg .u64 t; cvta.to.shared.u64 t, %1; cvt.u32.u64 %0, t; }" : "=r"(a) : "l"(p));
    return a;
}
__device__ __forceinline__ void cp16(uint32_t s, const void* g) {
    asm volatile("cp.async.cg.shared.global [%0], [%1], 16;" :: "r"(s), "l"(g) : "memory");
}
#define CP_COMMIT() asm volatile("cp.async.commit_group;" ::: "memory")
#define CP_WAIT2()  asm volatile("cp.async.wait_group 2;" ::: "memory")
#define CP_WAIT0()  asm volatile("cp.async.wait_group 0;" ::: "memory")

__device__ __forceinline__ void ldsm4(uint32_t* r, uint32_t addr) {
    asm volatile("ldmatrix.sync.aligned.m8n8.x4.shared.b16 {%0,%1,%2,%3}, [%4];"
                 : "=r"(r[0]), "=r"(r[1]), "=r"(r[2]), "=r"(r[3]) : "r"(addr));
}
__device__ __forceinline__ void hmma(float* c, const uint32_t* a, const uint32_t* b) {
    asm volatile("mma.sync.aligned.m16n8k16.row.col.f32.bf16.bf16.f32 "
                 "{%0,%1,%2,%3}, {%4,%5,%6,%7}, {%8,%9}, {%0,%1,%2,%3};"
                 : "+f"(c[0]), "+f"(c[1]), "+f"(c[2]), "+f"(c[3])
                 : "r"(a[0]), "r"(a[1]), "r"(a[2]), "r"(a[3]), "r"(b[0]), "r"(b[1]));
}

// ---------------- convert kernels ----------------
__device__ __forceinline__ void split_bf(float v, __nv_bfloat16& h, __nv_bfloat16& l) {
    h = __float2bfloat16(v);
    l = __float2bfloat16(v - __bfloat162float(h));
}

__global__ void conv_a(const float* __restrict__ x) {
    size_t gid = (size_t)blockIdx.x * blockDim.x + threadIdx.x;
    size_t base = gid * 4;
    size_t r = base / KD;
    size_t k = base % KD;
    float4 v = *(const float4*)(x + base);
    __nv_bfloat16 h[4], l[4];
    split_bf(v.x, h[0], l[0]); split_bf(v.y, h[1], l[1]);
    split_bf(v.z, h[2], l[2]); split_bf(v.w, h[3], l[3]);
    __nv_bfloat16* row = g_A + r * K3;
    #pragma unroll
    for (int i = 0; i < 4; i++) {
        row[k + i]          = h[i];
        row[KD + k + i]     = l[i];
        row[2 * KD + k + i] = h[i];
    }
}

__global__ void conv_b(const float* __restrict__ W) {
    __shared__ float t[32][33];
    int n0 = blockIdx.x * 32, k0 = blockIdx.y * 32;
    int tx = threadIdx.x, ty = threadIdx.y;    // 32 x 8
    #pragma unroll
    for (int i = 0; i < 4; i++)
        t[ty + 8 * i][tx] = W[(size_t)(k0 + ty + 8 * i) * NCOLS + n0 + tx];
    __syncthreads();
    #pragma unroll
    for (int i = 0; i < 4; i++) {
        int n = n0 + ty + 8 * i;
        int k = k0 + tx;
        float w = t[tx][ty + 8 * i];
        __nv_bfloat16 h, l;
        split_bf(w, h, l);
        __nv_bfloat16* row = g_B + (size_t)n * K3;
        row[k]          = h;
        row[KD + k]     = h;
        row[2 * KD + k] = l;
    }
}

__global__ void copy_pos(const float* __restrict__ pos) {
    int i = blockIdx.x * blockDim.x + threadIdx.x;
    if (i < Tn) g_posv[i] = pos[i];
}

// ---------------- main GEMM + fused epilogue ----------------
__global__ __launch_bounds__(256, 1)
void gemm_k(const float* __restrict__ gq, const float* __restrict__ gk,
            float* __restrict__ out) {
    extern __shared__ char smem[];
    const uint32_t TILES = smem_u32(smem);
    const int tid = threadIdx.x, wid = tid >> 5, lane = tid & 31;
    const int row0 = blockIdx.y << 7;
    const int col0 = blockIdx.x << 7;

    // warp mapping: wm (M-half), wn (N-half), kg (K-split)
    const int wm = wid >> 2, wn = (wid >> 1) & 1, kg = wid & 1;

    // producer mapping: each thread owns one smem row (64B per stage)
    const int prow = tid & 127;
    const int isB  = tid >= 128;
    const __nv_bfloat16* grow = isB
        ? (g_B + (size_t)(col0 + prow) * K3)
        : (g_A + (size_t)(row0 + prow) * K3);
    const uint32_t srowOff = (uint32_t)((isB ? ASTG : 0) + prow * ROWB);

    // ldmatrix per-lane offsets (within a stage)
    const uint32_t aLane = (uint32_t)((wm * 64 + (lane & 7) + ((lane >> 3) & 1) * 8) * ROWB
                                      + kg * 32 + (lane >> 4) * 16);
    const uint32_t bLane = (uint32_t)(ASTG + (wn * 64 + (lane & 7) + (lane >> 4) * 8) * ROWB
                                      + kg * 32 + ((lane >> 3) & 1) * 16);

    float acc[4][8][4];
    #pragma unroll
    for (int m = 0; m < 4; m++)
        #pragma unroll
        for (int n = 0; n < 8; n++)
            #pragma unroll
            for (int r = 0; r < 4; r++)
                acc[m][n][r] = 0.0f;

    // -------- prologue: prefetch NPIPE-1 stages --------
    #pragma unroll
    for (int f = 0; f < NPIPE - 1; f++) {
        const uint32_t d = TILES + f * STAGE_BYTES + srowOff;
        const char* g = (const char*)grow + (size_t)f * 64;
        cp16(d, g); cp16(d + 16, g + 16); cp16(d + 32, g + 32); cp16(d + 48, g + 48);
        CP_COMMIT();
    }

    // -------- mainloop --------
    for (int f = 0; f < NSTAGE; f++) {
        CP_WAIT2();
        __syncthreads();

        if (f + NPIPE - 1 < NSTAGE) {
            const uint32_t d = TILES + ((f + NPIPE - 1) & (NPIPE - 1)) * STAGE_BYTES + srowOff;
            const char* g = (const char*)grow + (size_t)(f + NPIPE - 1) * 64;
            cp16(d, g); cp16(d + 16, g + 16); cp16(d + 32, g + 32); cp16(d + 48, g + 48);
        }
        CP_COMMIT();

        const uint32_t sb = TILES + (f & (NPIPE - 1)) * STAGE_BYTES;
        uint32_t aR[4][4], bR[4][4];
        #pragma unroll
        for (int mt = 0; mt < 4; mt++) ldsm4(aR[mt], sb + aLane + mt * 16 * ROWB);
        #pragma unroll
        for (int nt2 = 0; nt2 < 4; nt2++) ldsm4(bR[nt2], sb + bLane + nt2 * 16 * ROWB);
        #pragma unroll
        for (int mt = 0; mt < 4; mt++)
            #pragma unroll
            for (int nt = 0; nt < 8; nt++)
                hmma(acc[mt][nt], aR[mt], &bR[nt >> 1][(nt & 1) * 2]);
    }
    CP_WAIT0();
    __syncthreads();

    // -------- combine K-split partials through smem fp32 tile (128x132) --------
    float* tile = (float*)smem;
    if (kg == 0) {
        #pragma unroll
        for (int mt = 0; mt < 4; mt++) {
            const int r = wm * 64 + mt * 16 + (lane >> 2);
            #pragma unroll
            for (int nt = 0; nt < 8; nt++) {
                const int c = wn * 64 + nt * 8 + 2 * (lane & 3);
                *(float2*)(tile + r * 132 + c)       = make_float2(acc[mt][nt][0], acc[mt][nt][1]);
                *(float2*)(tile + (r + 8) * 132 + c) = make_float2(acc[mt][nt][2], acc[mt][nt][3]);
            }
        }
    }
    __syncthreads();
    if (kg == 1) {
        #pragma unroll
        for (int mt = 0; mt < 4; mt++) {
            const int r = wm * 64 + mt * 16 + (lane >> 2);
            #pragma unroll
            for (int nt = 0; nt < 8; nt++) {
                const int c = wn * 64 + nt * 8 + 2 * (lane & 3);
                float2 v0 = *(float2*)(tile + r * 132 + c);
                float2 v1 = *(float2*)(tile + (r + 8) * 132 + c);
                v0.x += acc[mt][nt][0]; v0.y += acc[mt][nt][1];
                v1.x += acc[mt][nt][2]; v1.y += acc[mt][nt][3];
                *(float2*)(tile + r * 132 + c)       = v0;
                *(float2*)(tile + (r + 8) * 132 + c) = v1;
            }
        }
    }
    __syncthreads();

    // -------- fused RMSNorm + RoPE epilogue --------
    const int tx = tid & 15;
    const int ty = tid >> 4;
    const int region = col0 >> 11;          // 0=q, 1=k, 2=v
    const int colr0  = col0 & 2047;
    float* const outbase = out + (size_t)region * ((size_t)MROWS * DOUT);

    if (region == 2) {
        #pragma unroll
        for (int i = 0; i < 8; i++) {
            const int rr = ty * 8 + i;
            const float* s = tile + rr * 132 + tx * 8;
            float* p = outbase + (size_t)(row0 + rr) * DOUT + colr0 + tx * 8;
            *(float4*)(p + 0) = make_float4(s[0], s[1], s[2], s[3]);
            *(float4*)(p + 4) = make_float4(s[4], s[5], s[6], s[7]);
        }
        return;
    }

    const float* const g = (region == 0) ? gq : gk;
    float gv[8];
    #pragma unroll
    for (int j = 0; j < 8; j++) gv[j] = __ldg(g + tx * 8 + j);

    const float NLOG = -13.287712379549449f / 64.0f;   // -log2(10000)/64
    #pragma unroll
    for (int i = 0; i < 8; i++) {
        const int rr = ty * 8 + i;
        const int r  = row0 + rr;
        float v[8];
        const float* s = tile + rr * 132 + tx * 8;
        #pragma unroll
        for (int j = 0; j < 8; j++) v[j] = s[j];

        float ss = 0.0f;
        #pragma unroll
        for (int j = 0; j < 8; j++) ss += v[j] * v[j];
        ss += __shfl_xor_sync(0xffffffffu, ss, 1);
        ss += __shfl_xor_sync(0xffffffffu, ss, 2);
        ss += __shfl_xor_sync(0xffffffffu, ss, 4);
        ss += __shfl_xor_sync(0xffffffffu, ss, 8);
        const float rinv = rsqrtf(ss * (1.0f / 128.0f) + 1e-6f);
        const float pv = g_posv[r & (Tn - 1)];

        float o[8];
        #pragma unroll
        for (int j = 0; j < 8; j++) {
            const float val = v[j] * rinv * gv[j];
            const int   c   = tx * 8 + j;
            const float invf = exp2f((float)(c & 63) * NLOG);
            float sn, cs;
            sincosf(pv * invf, &sn, &cs);
            const float other = __shfl_xor_sync(0xffffffffu, val, 8);
            o[j] = (tx < 8) ? (val * cs - other * sn) : (other * sn + val * cs);
        }
        float* q = outbase + (size_t)r * DOUT + colr0 + tx * 8;
        *(float4*)(q + 0) = make_float4(o[0], o[1], o[2], o[3]);
        *(float4*)(q + 4) = make_float4(o[4], o[5], o[6], o[7]);
    }
}

extern "C" void kernel_launch(void* const* d_in, const int* in_sizes, int n_in,
                              void* d_out, int out_size) {
    const float* x   = (const float*)d_in[0];
    const float* W   = (const float*)d_in[1];
    const float* gq  = (const float*)d_in[2];
    const float* gk  = (const float*)d_in[3];
    const float* pos = (const float*)d_in[4];
    float* out = (float*)d_out;

    cudaFuncSetAttribute(gemm_k, cudaFuncAttributeMaxDynamicSharedMemorySize, SMEM_TOTAL);

    conv_a<<<(MROWS * KD / 4) / 256, 256>>>(x);
    conv_b<<<dim3(NCOLS / 32, KD / 32), dim3(32, 8)>>>(W);
    copy_pos<<<Tn / 256, 256>>>(pos);

    dim3 grid(NCOLS / 128, MROWS / 128);   // (48, 64)
    gemm_k<<<grid, 256, SMEM_TOTAL>>>(gq, gk, out);
}